// round 14
// baseline (speedup 1.0000x reference)
#include <cuda_runtime.h>
#include <cuda_bf16.h>
#include <stdint.h>
#include <math.h>

#define NROWS 32768
#define INDIM 2048
#define HID   1024
#define CSIZE 2048
#define TOPM  256
#define NCHUNK (CSIZE/128)   // 16 column-chunks of 128 codes
#define KC 64                // K per smem chunk (64 bf16 = 128B row, swizzle atom)

struct Pack { const float* p[16]; };
struct Meta { long long n[16]; int swap_tp; };

// ------------- scratch (__device__ globals) -------------
__device__ int   g_role[16];
__device__ float g_stat[16];
__device__ __nv_bfloat16 g_h0L[3][(size_t)NROWS * INDIM];
__device__ __nv_bfloat16 g_h1L[3][(size_t)NROWS * HID];
__device__ __nv_bfloat16 g_HL [3][(size_t)NROWS * HID];
__device__ float         g_H  [(size_t)NROWS * HID];
__device__ __nv_bfloat16 g_W1T[3][(size_t)HID * INDIM];
__device__ __nv_bfloat16 g_W2T[3][(size_t)HID * HID];
__device__ __nv_bfloat16 g_DT [3][3][(size_t)CSIZE * HID];
__device__ float g_invn[3][CSIZE];
__device__ float g_em  [3][CSIZE];
__device__ float g_pval [3][NROWS][NCHUNK];
__device__ float g_pval2[3][NROWS][NCHUNK];   // second-best per chunk
__device__ int   g_pidx [3][NROWS][NCHUNK];
__device__ unsigned long long g_keys[NROWS];
__device__ int   g_fixn;
__device__ int   g_fixlist[3 * NROWS];

// ---------------- helpers ----------------
__device__ __forceinline__ uint32_t smem_u32(const void* p) {
    uint32_t a;
    asm("{ .reg .u64 t; cvta.to.shared.u64 t, %1; cvt.u32.u64 %0, t; }" : "=r"(a) : "l"(p));
    return a;
}
#define SWZ128(o) ((o) ^ (((o) >> 3) & 0x70))

__device__ __forceinline__ void cpasync16(uint32_t dst, const void* src) {
    asm volatile("cp.async.cg.shared.global [%0], [%1], 16;" :: "r"(dst), "l"(src) : "memory");
}
#define CP_COMMIT() asm volatile("cp.async.commit_group;" ::: "memory")
#define CP_WAIT0()  asm volatile("cp.async.wait_group 0;" ::: "memory")

__device__ __forceinline__ void ldsm_x4(uint32_t& r0, uint32_t& r1, uint32_t& r2, uint32_t& r3, uint32_t a) {
    asm volatile("ldmatrix.sync.aligned.m8n8.x4.shared.b16 {%0,%1,%2,%3}, [%4];"
                 : "=r"(r0), "=r"(r1), "=r"(r2), "=r"(r3) : "r"(a));
}
__device__ __forceinline__ void mma_bf16(float* d, const uint32_t* a, const uint32_t* b) {
    asm volatile("mma.sync.aligned.m16n8k16.row.col.f32.bf16.bf16.f32 "
                 "{%0,%1,%2,%3}, {%4,%5,%6,%7}, {%8,%9}, {%0,%1,%2,%3};"
                 : "+f"(d[0]), "+f"(d[1]), "+f"(d[2]), "+f"(d[3])
                 : "r"(a[0]), "r"(a[1]), "r"(a[2]), "r"(a[3]), "r"(b[0]), "r"(b[1]));
}

__device__ __forceinline__ void split3(float f, __nv_bfloat16& h, __nv_bfloat16& m, __nv_bfloat16& l) {
    h = __float2bfloat16(f);
    float r1 = f - __bfloat162float(h);
    m = __float2bfloat16(r1);
    float r2 = r1 - __bfloat162float(m);
    l = __float2bfloat16(r2);
}

// =====================================================================================
// classify (proven)
// =====================================================================================
__global__ void classify_kernel(Pack pk, Meta mt)
{
    __shared__ float red[256];
    int tid = threadIdx.x;
    for (int i = 0; i < 16; i++) {
        long long n = mt.n[i];
        long long cnt = n < 16384 ? n : 16384;
        float s = 0.f;
        const float* p = pk.p[i];
        for (long long j = tid; j < cnt; j += blockDim.x) s += fabsf(p[j]);
        red[tid] = s;
        __syncthreads();
        for (int o = 128; o > 0; o >>= 1) {
            if (tid < o) red[tid] += red[tid + o];
            __syncthreads();
        }
        if (tid == 0) g_stat[i] = red[0] / (float)cnt;
        __syncthreads();
    }
    if (tid == 0) {
        int big[4], nb = 0, mid[4], nm = 0, sml[6], ns = 0, ih0 = 0, iksb = 0;
        for (int i = 0; i < 16; i++) {
            long long n = mt.n[i];
            if      (n == 67108864LL) ih0 = i;
            else if (n == 2097152LL && nb < 4) big[nb++] = i;
            else if (n == 1048576LL && nm < 4) mid[nm++] = i;
            else if (n == 1024LL    && ns < 6) sml[ns++] = i;
            else if (n == 1LL)       iksb = i;
        }
        int w1 = big[0];
        for (int t = 1; t < 4; t++) if (g_stat[big[t]] < g_stat[w1]) w1 = big[t];
        int cA[3], ncv = 0;
        for (int t = 0; t < 4; t++) if (big[t] != w1) cA[ncv++] = big[t];
        int ksw = sml[0];
        for (int t = 1; t < 6; t++) if (g_stat[sml[t]] > g_stat[ksw]) ksw = sml[t];
        int bA[5], nbv = 0;
        for (int t = 0; t < 6; t++) if (sml[t] != ksw) bA[nbv++] = sml[t];

        int sw = mt.swap_tp;
        g_role[0]  = ih0;  g_role[1]  = w1;   g_role[2]  = bA[0];
        g_role[3]  = mid[0]; g_role[4]  = bA[1]; g_role[5]  = mid[1]; g_role[6]  = bA[2];
        g_role[7]  = sw ? mid[3] : mid[2];  g_role[8]  = sw ? bA[4]  : bA[3];
        g_role[9]  = sw ? mid[2] : mid[3];  g_role[10] = sw ? bA[3]  : bA[4];
        g_role[11] = cA[0];
        g_role[12] = sw ? cA[2] : cA[1];    g_role[13] = sw ? cA[1] : cA[2];
        g_role[14] = ksw;  g_role[15] = iksb;
    }
}

// =====================================================================================
__global__ void split_h0(Pack pk)
{
    size_t i = ((size_t)blockIdx.x * blockDim.x + threadIdx.x) * 4;
    const float* src = pk.p[g_role[0]];
    if (i >= (size_t)NROWS * INDIM) return;
    float4 v = *(const float4*)(src + i);
    __nv_bfloat16 h[4], m[4], l[4];
    split3(v.x, h[0], m[0], l[0]); split3(v.y, h[1], m[1], l[1]);
    split3(v.z, h[2], m[2], l[2]); split3(v.w, h[3], m[3], l[3]);
    #pragma unroll
    for (int j = 0; j < 2; j++) {
        __nv_bfloat162 p;
        p.x = h[j*2]; p.y = h[j*2+1]; *(__nv_bfloat162*)(&g_h0L[0][i + j*2]) = p;
        p.x = m[j*2]; p.y = m[j*2+1]; *(__nv_bfloat162*)(&g_h0L[1][i + j*2]) = p;
        p.x = l[j*2]; p.y = l[j*2+1]; *(__nv_bfloat162*)(&g_h0L[2][i + j*2]) = p;
    }
}

// =====================================================================================
__global__ void splitT_W(Pack pk, int which)
{
    int K = which ? HID : INDIM;
    const float* src = pk.p[g_role[which ? 3 : 1]];
    size_t idx = (size_t)blockIdx.x * blockDim.x + threadIdx.x;
    if (idx >= (size_t)K * HID) return;
    size_t k = idx / HID, n = idx % HID;
    __nv_bfloat16 h, m, l;
    split3(src[idx], h, m, l);
    size_t o = n * (size_t)K + k;
    if (which == 0) { g_W1T[0][o] = h; g_W1T[1][o] = m; g_W1T[2][o] = l; }
    else            { g_W2T[0][o] = h; g_W2T[1][o] = m; g_W2T[2][o] = l; }
}

// =====================================================================================
// D = W @ C^T (fp32 SIMT), writes transposed bf16 limbs g_DT[l][mod][c][j]
// =====================================================================================
__global__ void __launch_bounds__(256) wct_gemm(Pack pk, int mod)
{
    const float* W  = pk.p[g_role[5 + 2 * mod]];
    const float* Cb = pk.p[g_role[11 + mod]];

    __shared__ float As[16][132];
    __shared__ float Bs[16][132];

    int tid = threadIdx.x;
    int tx = tid & 15, ty = tid >> 4;
    int bm = blockIdx.y * 128;
    int bn = blockIdx.x * 128;

    float acc[8][8] = {};

    for (int kt = 0; kt < HID; kt += 16) {
        #pragma unroll
        for (int i = 0; i < 2; i++) {
            int f = tid + i * 256;
            int m = f >> 2, k4 = (f & 3) << 2;
            float4 v = *(const float4*)(W + (size_t)(bm + m) * HID + kt + k4);
            As[k4 + 0][m] = v.x; As[k4 + 1][m] = v.y;
            As[k4 + 2][m] = v.z; As[k4 + 3][m] = v.w;
        }
        #pragma unroll
        for (int i = 0; i < 2; i++) {
            int f = tid + i * 256;
            int c = f >> 2, k4 = (f & 3) << 2;
            float4 v = *(const float4*)(Cb + (size_t)(bn + c) * HID + kt + k4);
            Bs[k4 + 0][c] = v.x; Bs[k4 + 1][c] = v.y;
            Bs[k4 + 2][c] = v.z; Bs[k4 + 3][c] = v.w;
        }
        __syncthreads();

        #pragma unroll
        for (int k = 0; k < 16; k++) {
            float a[8], b[8];
            *(float4*)(a)     = *(const float4*)(&As[k][ty * 8]);
            *(float4*)(a + 4) = *(const float4*)(&As[k][ty * 8 + 4]);
            *(float4*)(b)     = *(const float4*)(&Bs[k][tx * 8]);
            *(float4*)(b + 4) = *(const float4*)(&Bs[k][tx * 8 + 4]);
            #pragma unroll
            for (int i = 0; i < 8; i++)
                #pragma unroll
                for (int j = 0; j < 8; j++)
                    acc[i][j] = fmaf(a[i], b[j], acc[i][j]);
        }
        __syncthreads();
    }

    #pragma unroll
    for (int i = 0; i < 8; i++) {
        int jrow = bm + ty * 8 + i;
        #pragma unroll
        for (int j = 0; j < 8; j++) {
            int c = bn + tx * 8 + j;
            __nv_bfloat16 h, m, l;
            split3(acc[i][j], h, m, l);
            size_t o = (size_t)c * HID + jrow;
            g_DT[0][mod][o] = h; g_DT[1][mod][o] = m; g_DT[2][mod][o] = l;
        }
    }
}

// =====================================================================================
__global__ void prep_kernel(Pack pk, int mod)
{
    const float* Cb   = pk.p[g_role[11 + mod]];
    const float* bvec = pk.p[g_role[6 + 2 * mod]];

    int row  = (blockIdx.x * blockDim.x + threadIdx.x) >> 5;
    int lane = threadIdx.x & 31;
    if (row >= CSIZE) return;
    const float* c = Cb + (size_t)row * HID;
    float s = 0.f, e = 0.f;
    for (int i = lane; i < HID; i += 32) {
        float cv = c[i];
        s = fmaf(cv, cv, s);
        e = fmaf(bvec[i], cv, e);
    }
    #pragma unroll
    for (int o = 16; o > 0; o >>= 1) {
        s += __shfl_xor_sync(0xFFFFFFFFu, s, o);
        e += __shfl_xor_sync(0xFFFFFFFFu, e, o);
    }
    if (lane == 0) {
        g_invn[mod][row] = 1.0f / sqrtf(s + 1e-12f);
        g_em[mod][row]   = e;
    }
}

// =====================================================================================
// bf16x6 HMMA GEMM (structure proven in round 13; VQ epilogue now tracks top-2)
// =====================================================================================
#define STG_BYTES 98304
#define SMEM_HM   (2 * STG_BYTES)

__global__ void __launch_bounds__(256) hmma_gemm(Pack pk, int which)
{
    extern __shared__ __align__(1024) unsigned char dsm[];
    __shared__ float rv_s[128][2];
    __shared__ float sv_s[128][2];
    __shared__ int   ri_s[128][2];

    const __nv_bfloat16* AL[3];
    const __nv_bfloat16* BL[3];
    const float* bias = 0;
    long K; int mode, mod = 0;
    if (which == 0) {
        AL[0]=g_h0L[0]; AL[1]=g_h0L[1]; AL[2]=g_h0L[2];
        BL[0]=g_W1T[0]; BL[1]=g_W1T[1]; BL[2]=g_W1T[2];
        bias = pk.p[g_role[2]]; K = INDIM; mode = 0;
    } else if (which == 1) {
        AL[0]=g_h1L[0]; AL[1]=g_h1L[1]; AL[2]=g_h1L[2];
        BL[0]=g_W2T[0]; BL[1]=g_W2T[1]; BL[2]=g_W2T[2];
        bias = pk.p[g_role[4]]; K = HID; mode = 1;
    } else {
        mod = which - 2;
        AL[0]=g_HL[0];  AL[1]=g_HL[1];  AL[2]=g_HL[2];
        BL[0]=g_DT[0][mod]; BL[1]=g_DT[1][mod]; BL[2]=g_DT[2][mod];
        K = HID; mode = 2;
    }

    int tid = threadIdx.x, lane = tid & 31, wid = tid >> 5;
    int wm = wid & 3, wn = wid >> 2;
    int bm = blockIdx.y * 128, bn = blockIdx.x * 128;
    uint32_t sb = smem_u32(dsm);
    int Kch = (int)(K / KC);

    float acc[2][8][4];
    #pragma unroll
    for (int a = 0; a < 2; a++)
        #pragma unroll
        for (int b = 0; b < 8; b++)
            #pragma unroll
            for (int c = 0; c < 4; c++) acc[a][b][c] = 0.f;

    auto load_chunk = [&](int ch, int stage) {
        uint32_t base = sb + stage * STG_BYTES;
        int kt = ch * KC;
        #pragma unroll
        for (int l = 0; l < 3; l++) {
            #pragma unroll
            for (int i = 0; i < 4; i++) {
                int s = tid + i * 256;
                int row = s >> 3, seg = s & 7;
                uint32_t off = SWZ128((uint32_t)row * 128u + (uint32_t)seg * 16u);
                cpasync16(base + l * 16384 + off,
                          AL[l] + (size_t)(bm + row) * K + kt + seg * 8);
                cpasync16(base + 49152 + l * 16384 + off,
                          BL[l] + (size_t)(bn + row) * K + kt + seg * 8);
            }
        }
        CP_COMMIT();
    };

    const int PA[6] = {2, 1, 0, 1, 0, 0};
    const int PB[6] = {0, 1, 2, 0, 1, 0};

    load_chunk(0, 0);

    for (int ch = 0; ch < Kch; ch++) {
        CP_WAIT0();
        __syncthreads();
        if (ch + 1 < Kch) load_chunk(ch + 1, (ch + 1) & 1);

        uint32_t sA = sb + (ch & 1) * STG_BYTES;
        uint32_t sB = sA + 49152;

        #pragma unroll
        for (int p = 0; p < 6; p++) {
            uint32_t ab = sA + PA[p] * 16384;
            uint32_t bb = sB + PB[p] * 16384;
            #pragma unroll
            for (int q = 0; q < 4; q++) {
                uint32_t afr[2][4];
                #pragma unroll
                for (int mt = 0; mt < 2; mt++) {
                    int row = wm * 32 + mt * 16 + (lane & 7) + ((lane >> 3) & 1) * 8;
                    int seg = q * 2 + (lane >> 4);
                    ldsm_x4(afr[mt][0], afr[mt][1], afr[mt][2], afr[mt][3],
                            ab + SWZ128((uint32_t)row * 128u + (uint32_t)seg * 16u));
                }
                uint32_t bfr[8][2];
                #pragma unroll
                for (int nt2 = 0; nt2 < 4; nt2++) {
                    int nr  = wn * 64 + nt2 * 16 + (lane & 7) + (lane >> 4) * 8;
                    int seg = q * 2 + ((lane >> 3) & 1);
                    uint32_t r0, r1, r2, r3;
                    ldsm_x4(r0, r1, r2, r3,
                            bb + SWZ128((uint32_t)nr * 128u + (uint32_t)seg * 16u));
                    bfr[nt2 * 2][0] = r0; bfr[nt2 * 2][1] = r1;
                    bfr[nt2 * 2 + 1][0] = r2; bfr[nt2 * 2 + 1][1] = r3;
                }
                #pragma unroll
                for (int mt = 0; mt < 2; mt++)
                    #pragma unroll
                    for (int nt = 0; nt < 8; nt++)
                        mma_bf16(acc[mt][nt], afr[mt], bfr[nt]);
            }
        }
        __syncthreads();
    }

    // ---- epilogue ----
    if (mode < 2) {
        __nv_bfloat16* O0 = mode ? g_HL[0] : g_h1L[0];
        __nv_bfloat16* O1 = mode ? g_HL[1] : g_h1L[1];
        __nv_bfloat16* O2 = mode ? g_HL[2] : g_h1L[2];
        #pragma unroll
        for (int mt = 0; mt < 2; mt++) {
            #pragma unroll
            for (int nt = 0; nt < 8; nt++) {
                int r0 = bm + wm * 32 + mt * 16 + (lane >> 2);
                int c0 = bn + wn * 64 + nt * 8 + (lane & 3) * 2;
                #pragma unroll
                for (int h = 0; h < 2; h++) {
                    int row = r0 + h * 8;
                    float v0 = fmaxf(acc[mt][nt][h * 2 + 0] + bias[c0], 0.f);
                    float v1 = fmaxf(acc[mt][nt][h * 2 + 1] + bias[c0 + 1], 0.f);
                    __nv_bfloat16 h0, m0, l0, h1, m1, l1;
                    split3(v0, h0, m0, l0); split3(v1, h1, m1, l1);
                    size_t o = (size_t)row * HID + c0;
                    __nv_bfloat162 pr;
                    pr.x = h0; pr.y = h1; *(__nv_bfloat162*)(O0 + o) = pr;
                    pr.x = m0; pr.y = m1; *(__nv_bfloat162*)(O1 + o) = pr;
                    pr.x = l0; pr.y = l1; *(__nv_bfloat162*)(O2 + o) = pr;
                    if (mode == 1) { float2 f2; f2.x = v0; f2.y = v1; *(float2*)(g_H + o) = f2; }
                }
            }
        }
    } else {
        // top-2 argmax over this block's 128 codes
        float bv[2][2], sv[2][2]; int bi[2][2];
        #pragma unroll
        for (int mt = 0; mt < 2; mt++)
            #pragma unroll
            for (int h = 0; h < 2; h++) { bv[mt][h] = -INFINITY; sv[mt][h] = -INFINITY; bi[mt][h] = 0; }
        #pragma unroll
        for (int nt = 0; nt < 8; nt++) {
            int c0 = bn + wn * 64 + nt * 8 + (lane & 3) * 2;
            float e0 = g_em[mod][c0],     n0 = g_invn[mod][c0];
            float e1 = g_em[mod][c0 + 1], n1 = g_invn[mod][c0 + 1];
            #pragma unroll
            for (int mt = 0; mt < 2; mt++)
                #pragma unroll
                for (int h = 0; h < 2; h++) {
                    float v0 = (acc[mt][nt][h * 2 + 0] + e0) * n0;
                    float v1 = (acc[mt][nt][h * 2 + 1] + e1) * n1;
                    if (v0 > bv[mt][h] || (v0 == bv[mt][h] && c0 < bi[mt][h])) {
                        sv[mt][h] = bv[mt][h]; bv[mt][h] = v0; bi[mt][h] = c0;
                    } else if (v0 > sv[mt][h]) sv[mt][h] = v0;
                    int c1 = c0 + 1;
                    if (v1 > bv[mt][h] || (v1 == bv[mt][h] && c1 < bi[mt][h])) {
                        sv[mt][h] = bv[mt][h]; bv[mt][h] = v1; bi[mt][h] = c1;
                    } else if (v1 > sv[mt][h]) sv[mt][h] = v1;
                }
        }
        #pragma unroll
        for (int off = 1; off <= 2; off <<= 1) {
            #pragma unroll
            for (int mt = 0; mt < 2; mt++)
                #pragma unroll
                for (int h = 0; h < 2; h++) {
                    float ov  = __shfl_xor_sync(0xFFFFFFFFu, bv[mt][h], off);
                    int   oi  = __shfl_xor_sync(0xFFFFFFFFu, bi[mt][h], off);
                    float osv = __shfl_xor_sync(0xFFFFFFFFu, sv[mt][h], off);
                    if (ov > bv[mt][h] || (ov == bv[mt][h] && oi < bi[mt][h])) {
                        sv[mt][h] = fmaxf(bv[mt][h], osv);
                        bv[mt][h] = ov; bi[mt][h] = oi;
                    } else {
                        sv[mt][h] = fmaxf(sv[mt][h], ov);
                    }
                }
        }
        if ((lane & 3) == 0) {
            #pragma unroll
            for (int mt = 0; mt < 2; mt++)
                #pragma unroll
                for (int h = 0; h < 2; h++) {
                    int rloc = wm * 32 + mt * 16 + (lane >> 2) + h * 8;
                    rv_s[rloc][wn] = bv[mt][h];
                    sv_s[rloc][wn] = sv[mt][h];
                    ri_s[rloc][wn] = bi[mt][h];
                }
        }
        __syncthreads();
        if (tid < 128) {
            float v0 = rv_s[tid][0], v1 = rv_s[tid][1];
            float s0 = sv_s[tid][0], s1 = sv_s[tid][1];
            int   i0 = ri_s[tid][0], i1 = ri_s[tid][1];
            float tb, ts; int ti;
            if (v1 > v0 || (v1 == v0 && i1 < i0)) { tb = v1; ti = i1; ts = fmaxf(v0, s1); }
            else                                  { tb = v0; ti = i0; ts = fmaxf(s0, v1); }
            g_pval [mod][bm + tid][blockIdx.x] = tb;
            g_pval2[mod][bm + tid][blockIdx.x] = ts;
            g_pidx [mod][bm + tid][blockIdx.x] = ti;
        }
    }
}

// =====================================================================================
__global__ void init_fix() { if (threadIdx.x == 0 && blockIdx.x == 0) g_fixn = 0; }

// =====================================================================================
// reduce codes (global top-2 merge) + margin flagging
// =====================================================================================
__global__ void reduce_codes(float* __restrict__ out)
{
    int n = blockIdx.x * blockDim.x + threadIdx.x;
    if (n >= NROWS) return;
    #pragma unroll
    for (int m = 0; m < 3; m++) {
        float bv = g_pval[m][n][0]; int bi = g_pidx[m][n][0];
        float sv = g_pval2[m][n][0];
        #pragma unroll
        for (int c = 1; c < NCHUNK; c++) {
            float v  = g_pval [m][n][c];
            float v2 = g_pval2[m][n][c];
            if (v > bv) { sv = fmaxf(bv, v2); bv = v; bi = g_pidx[m][n][c]; }
            else        { sv = fmaxf(sv, v); }
        }
        out[n * 3 + m] = (float)bi;
        // margin-based flag for exact recompute (threshold >> realized noise)
        if (bv - sv < 4e-3f * fmaxf(fabsf(bv), 1.0f)) {
            int slot = atomicAdd(&g_fixn, 1);
            g_fixlist[slot] = (m << 16) | n;
        }
    }
}

// =====================================================================================
// exact fp32 repair for near-tie rows: h0 -> h1 -> H -> z -> full 2048-code argmax
// =====================================================================================
__global__ void __launch_bounds__(256) fix_kernel(Pack pk, float* __restrict__ out)
{
    __shared__ float s1[HID];
    __shared__ float s2[HID];
    __shared__ float rbv[256];
    __shared__ int   rbi[256];

    int tid = threadIdx.x;
    int total = g_fixn;

    for (int it = blockIdx.x; it < total; it += gridDim.x) {
        int enc = g_fixlist[it];
        int m = enc >> 16, n = enc & 0xFFFF;
        const float* h0 = pk.p[g_role[0]] + (size_t)n * INDIM;
        const float* W1 = pk.p[g_role[1]];
        const float* b1 = pk.p[g_role[2]];
        const float* W2 = pk.p[g_role[3]];
        const float* b2 = pk.p[g_role[4]];
        const float* Wm = pk.p[g_role[5 + 2 * m]];
        const float* bm = pk.p[g_role[6 + 2 * m]];
        const float* Cb = pk.p[g_role[11 + m]];

        for (int j = tid; j < HID; j += 256) {
            float s = 0.f;
            for (int k = 0; k < INDIM; k++) s = fmaf(h0[k], W1[(size_t)k * HID + j], s);
            s1[j] = fmaxf(s + b1[j], 0.f);
        }
        __syncthreads();
        for (int j = tid; j < HID; j += 256) {
            float s = 0.f;
            for (int k = 0; k < HID; k++) s = fmaf(s1[k], W2[(size_t)k * HID + j], s);
            s2[j] = fmaxf(s + b2[j], 0.f);
        }
        __syncthreads();
        for (int j = tid; j < HID; j += 256) {
            float s = 0.f;
            for (int k = 0; k < HID; k++) s = fmaf(s2[k], Wm[(size_t)k * HID + j], s);
            s1[j] = s + bm[j];       // z (overwrites h1; safe after sync)
        }
        __syncthreads();

        float bb = -INFINITY; int bidx = CSIZE;
        for (int c = tid; c < CSIZE; c += 256) {
            const float* cr = Cb + (size_t)c * HID;
            float s = 0.f;
            for (int k = 0; k < HID; k++) s = fmaf(s1[k], cr[k], s);
            float v = s * g_invn[m][c];
            if (v > bb) { bb = v; bidx = c; }     // c ascending per thread: keeps lowest
        }
        rbv[tid] = bb; rbi[tid] = bidx;
        __syncthreads();
        for (int o = 128; o > 0; o >>= 1) {
            if (tid < o) {
                float v2 = rbv[tid + o]; int i2 = rbi[tid + o];
                if (v2 > rbv[tid] || (v2 == rbv[tid] && i2 < rbi[tid])) { rbv[tid] = v2; rbi[tid] = i2; }
            }
            __syncthreads();
        }
        if (tid == 0) out[n * 3 + m] = (float)rbi[0];
        __syncthreads();
    }
}

// =====================================================================================
__global__ void score_kernel(Pack pk)
{
    const float* ksw = pk.p[g_role[14]];
    const float* ksb = pk.p[g_role[15]];
    int warp = (blockIdx.x * blockDim.x + threadIdx.x) >> 5;
    int lane = threadIdx.x & 31;
    if (warp >= NROWS) return;
    const float* h = g_H + (size_t)warp * HID;
    double s = 0.0;
    for (int i = lane; i < HID; i += 32) s += (double)h[i] * (double)ksw[i];
    #pragma unroll
    for (int o = 16; o > 0; o >>= 1) s += __shfl_xor_sync(0xFFFFFFFFu, s, o);
    if (lane == 0) {
        float sc = (float)(s + (double)ksb[0]);
        unsigned int b = __float_as_uint(sc);
        b = (b & 0x80000000u) ? ~b : (b | 0x80000000u);
        g_keys[warp] = ((unsigned long long)b << 32) | (0xFFFFFFFFu - (unsigned)warp);
    }
}

// =====================================================================================
__global__ void topk_kernel(float* __restrict__ out)
{
    __shared__ unsigned int hist[256];
    __shared__ unsigned long long sprefix;
    __shared__ int skk;
    __shared__ unsigned long long skeys[TOPM];
    __shared__ unsigned int scount;

    int tid = threadIdx.x;
    if (tid == 0) { sprefix = 0ULL; skk = TOPM; scount = 0u; }
    __syncthreads();

    for (int p = 7; p >= 0; p--) {
        if (tid < 256) hist[tid] = 0u;
        __syncthreads();
        unsigned long long pref = sprefix;
        for (int i = tid; i < NROWS; i += blockDim.x) {
            unsigned long long k = g_keys[i];
            bool match = (p == 7) || ((k >> ((p + 1) * 8)) == pref);
            if (match) atomicAdd(&hist[(unsigned)(k >> (p * 8)) & 0xFFu], 1u);
        }
        __syncthreads();
        if (tid == 0) {
            int kk = skk, c = 0, d;
            for (d = 255; d >= 0; d--) { c += (int)hist[d]; if (c >= kk) break; }
            skk = kk - (c - (int)hist[d]);
            sprefix = (sprefix << 8) | (unsigned long long)d;
        }
        __syncthreads();
    }
    unsigned long long thr = sprefix;

    for (int i = tid; i < NROWS; i += blockDim.x) {
        unsigned long long k = g_keys[i];
        if (k >= thr) {
            unsigned p = atomicAdd(&scount, 1u);
            if (p < TOPM) skeys[p] = k;
        }
    }
    __syncthreads();

    for (int sz = 2; sz <= TOPM; sz <<= 1) {
        for (int st = sz >> 1; st > 0; st >>= 1) {
            __syncthreads();
            if (tid < TOPM) {
                int ixj = tid ^ st;
                if (ixj > tid) {
                    unsigned long long a = skeys[tid], b = skeys[ixj];
                    bool descBlk = ((tid & sz) == 0);
                    if (descBlk ? (a < b) : (a > b)) { skeys[tid] = b; skeys[ixj] = a; }
                }
            }
        }
    }
    __syncthreads();

    if (tid < TOPM) {
        unsigned idx = 0xFFFFFFFFu - (unsigned)(skeys[tid] & 0xFFFFFFFFu);
        out[NROWS * 3 + tid] = (float)idx;
        #pragma unroll
        for (int m = 0; m < 3; m++)
            out[NROWS * 3 + TOPM + tid * 3 + m] = out[(size_t)idx * 3 + m];
    }
}

// =====================================================================================
extern "C" void kernel_launch(void* const* d_in, const int* in_sizes, int n_in,
                              void* d_out, int out_size)
{
    Pack pk;
    Meta mt;
    int n16 = n_in < 16 ? n_in : 16;

    long long mn = 0x7FFFFFFFFFFFFFFFLL;
    for (int i = 0; i < n16; i++) {
        long long s = (long long)in_sizes[i];
        if (s < mn) mn = s;
    }
    long long div = (mn == 4) ? 4 : 1;

    for (int i = 0; i < 16; i++) {
        int src = i < n16 ? i : (n16 - 1);
        pk.p[i] = (const float*)d_in[src];
        mt.n[i] = (long long)in_sizes[src] / div;
    }

    mt.swap_tp = 0;
    if (mt.n[13] == 67108864LL) mt.swap_tp = 1;
    else if (mt.n[8] == 67108864LL && mt.n[0] == 1024LL) mt.swap_tp = 1;

    float* out = (float*)d_out;

    static int smem_set = 0;
    if (!smem_set) {
        cudaFuncSetAttribute(hmma_gemm, cudaFuncAttributeMaxDynamicSharedMemorySize, SMEM_HM);
        smem_set = 1;
    }

    dim3 blk(256);
    dim3 gWCT(CSIZE / 128, HID / 128);      // (16, 8)
    dim3 gMLP(HID / 128,   NROWS / 128);    // (8, 256)
    dim3 gVQ (CSIZE / 128, NROWS / 128);    // (16, 256)

    classify_kernel<<<1, 256>>>(pk, mt);                              // 1
    split_h0<<<(NROWS * INDIM / 4 + 255) / 256, 256>>>(pk);           // 2
    splitT_W<<<(INDIM * HID + 255) / 256, 256>>>(pk, 0);              // 3
    splitT_W<<<(HID * HID + 255) / 256, 256>>>(pk, 1);                // 4
    wct_gemm<<<gWCT, blk>>>(pk, 0);                                   // 5
    hmma_gemm<<<gMLP, blk, SMEM_HM>>>(pk, 0);                         // 6: MLP1 <- profiled
    hmma_gemm<<<gMLP, blk, SMEM_HM>>>(pk, 1);                         // 7: MLP2
    prep_kernel<<<CSIZE / 8, 256>>>(pk, 0);                           // 8
    hmma_gemm<<<gVQ, blk, SMEM_HM>>>(pk, 2);                          // 9: VQ mod 0
    wct_gemm<<<gWCT, blk>>>(pk, 1);
    prep_kernel<<<CSIZE / 8, 256>>>(pk, 1);
    hmma_gemm<<<gVQ, blk, SMEM_HM>>>(pk, 3);                          // VQ mod 1
    wct_gemm<<<gWCT, blk>>>(pk, 2);
    prep_kernel<<<CSIZE / 8, 256>>>(pk, 2);
    hmma_gemm<<<gVQ, blk, SMEM_HM>>>(pk, 4);                          // VQ mod 2

    init_fix<<<1, 32>>>();
    reduce_codes<<<NROWS / 256, 256>>>(out);
    fix_kernel<<<1024, 256>>>(pk, out);
    score_kernel<<<NROWS / 8, 256>>>(pk);
    topk_kernel<<<1, 1024>>>(out);
}

// round 15
// speedup vs baseline: 3.7296x; 3.7296x over previous
#include <cuda_runtime.h>
#include <stdint.h>
#include <math.h>

#define NROWS 32768
#define INDIM 2048
#define HID   1024
#define CSIZE 2048
#define TOPM  256
#define NCHUNK (CSIZE/128)   // 16 column-chunks of 128 codes

// Role indices: 0:h0 1:W1 2:b1 3:W2 4:b2 5:Wm 6:bm 7:Wt 8:bt 9:Wp 10:bp
//               11:Cm 12:Ct 13:Cp 14:ksw 15:ksb
struct Pack { const float* p[16]; };
struct Meta { long long n[16]; int swap_tp; };

// ------------- scratch: __device__ globals (allocation-free) -------------
__device__ int   g_role[16];
__device__ float g_stat[16];
__device__ float g_h1[(size_t)NROWS * HID];            // 128 MB fp32
__device__ float g_H [(size_t)NROWS * HID];            // 128 MB fp32
__device__ float g_D [3][HID * CSIZE];                 // 24 MB: D = W @ C^T per modality
__device__ float g_invn[3][CSIZE];
__device__ float g_em  [3][CSIZE];
__device__ float g_pval[3][NROWS][NCHUNK];
__device__ int   g_pidx[3][NROWS][NCHUNK];
__device__ unsigned long long g_keys[NROWS];

// =====================================================================================
// classify: proven (round 10/14)
// =====================================================================================
__global__ void classify_kernel(Pack pk, Meta mt)
{
    __shared__ float red[256];
    int tid = threadIdx.x;
    for (int i = 0; i < 16; i++) {
        long long n = mt.n[i];
        long long cnt = n < 16384 ? n : 16384;
        float s = 0.f;
        const float* p = pk.p[i];
        for (long long j = tid; j < cnt; j += blockDim.x) s += fabsf(p[j]);
        red[tid] = s;
        __syncthreads();
        for (int o = 128; o > 0; o >>= 1) {
            if (tid < o) red[tid] += red[tid + o];
            __syncthreads();
        }
        if (tid == 0) g_stat[i] = red[0] / (float)cnt;
        __syncthreads();
    }
    if (tid == 0) {
        int big[4], nb = 0, mid[4], nm = 0, sml[6], ns = 0, ih0 = 0, iksb = 0;
        for (int i = 0; i < 16; i++) {
            long long n = mt.n[i];
            if      (n == 67108864LL) ih0 = i;
            else if (n == 2097152LL && nb < 4) big[nb++] = i;
            else if (n == 1048576LL && nm < 4) mid[nm++] = i;
            else if (n == 1024LL    && ns < 6) sml[ns++] = i;
            else if (n == 1LL)       iksb = i;
        }
        int w1 = big[0];
        for (int t = 1; t < 4; t++) if (g_stat[big[t]] < g_stat[w1]) w1 = big[t];
        int cA[3], ncv = 0;
        for (int t = 0; t < 4; t++) if (big[t] != w1) cA[ncv++] = big[t];
        int ksw = sml[0];
        for (int t = 1; t < 6; t++) if (g_stat[sml[t]] > g_stat[ksw]) ksw = sml[t];
        int bA[5], nbv = 0;
        for (int t = 0; t < 6; t++) if (sml[t] != ksw) bA[nbv++] = sml[t];

        int sw = mt.swap_tp;
        g_role[0]  = ih0;  g_role[1]  = w1;   g_role[2]  = bA[0];
        g_role[3]  = mid[0]; g_role[4]  = bA[1]; g_role[5]  = mid[1]; g_role[6]  = bA[2];
        g_role[7]  = sw ? mid[3] : mid[2];  g_role[8]  = sw ? bA[4]  : bA[3];
        g_role[9]  = sw ? mid[2] : mid[3];  g_role[10] = sw ? bA[3]  : bA[4];
        g_role[11] = cA[0];
        g_role[12] = sw ? cA[2] : cA[1];    g_role[13] = sw ? cA[1] : cA[2];
        g_role[14] = ksw;  g_role[15] = iksb;
    }
}

// =====================================================================================
// MLP GEMM: dst = relu(A @ W + bias).  128x128x16 tile, 256 threads, 8x8/thread.
// __launch_bounds__(256, 2): cap regs so 2 CTAs co-reside per SM (issue-latency hiding).
// =====================================================================================
__global__ void __launch_bounds__(256, 2) mlp_gemm(Pack pk, int which, int K)
{
    const float* A    = which ? g_h1 : pk.p[g_role[0]];
    const float* W    = pk.p[g_role[which ? 3 : 1]];
    const float* bias = pk.p[g_role[which ? 4 : 2]];
    float*       Cd   = which ? g_H : g_h1;

    __shared__ float As[16][132];
    __shared__ float Bs[16][132];

    int tid = threadIdx.x;
    int tx = tid & 15, ty = tid >> 4;
    int bm = blockIdx.y * 128;
    int bn = blockIdx.x * 128;

    float acc[8][8] = {};

    for (int kt = 0; kt < K; kt += 16) {
        #pragma unroll
        for (int i = 0; i < 2; i++) {
            int f = tid + i * 256;
            int m = f >> 2, k4 = (f & 3) << 2;
            float4 v = *(const float4*)(A + (size_t)(bm + m) * K + kt + k4);
            As[k4 + 0][m] = v.x; As[k4 + 1][m] = v.y;
            As[k4 + 2][m] = v.z; As[k4 + 3][m] = v.w;
        }
        #pragma unroll
        for (int i = 0; i < 2; i++) {
            int f = tid + i * 256;
            int k = f >> 5, n4 = (f & 31) << 2;
            *(float4*)(&Bs[k][n4]) =
                *(const float4*)(W + (size_t)(kt + k) * HID + bn + n4);
        }
        __syncthreads();

        #pragma unroll
        for (int k = 0; k < 16; k++) {
            float a[8], b[8];
            *(float4*)(a)     = *(const float4*)(&As[k][ty * 8]);
            *(float4*)(a + 4) = *(const float4*)(&As[k][ty * 8 + 4]);
            *(float4*)(b)     = *(const float4*)(&Bs[k][tx * 8]);
            *(float4*)(b + 4) = *(const float4*)(&Bs[k][tx * 8 + 4]);
            #pragma unroll
            for (int i = 0; i < 8; i++)
                #pragma unroll
                for (int j = 0; j < 8; j++)
                    acc[i][j] = fmaf(a[i], b[j], acc[i][j]);
        }
        __syncthreads();
    }

    #pragma unroll
    for (int i = 0; i < 8; i++) {
        int row = bm + ty * 8 + i;
        #pragma unroll
        for (int j4 = 0; j4 < 8; j4 += 4) {
            float4 o; float* op = (float*)&o;
            #pragma unroll
            for (int j = 0; j < 4; j++) {
                float v = acc[i][j4 + j] + bias[bn + tx * 8 + j4 + j];
                op[j] = fmaxf(v, 0.f);
            }
            *(float4*)(Cd + (size_t)row * HID + bn + tx * 8 + j4) = o;
        }
    }
}

// =====================================================================================
// D = W @ C^T for all 3 modalities in ONE launch (blockIdx.z = mod).
// =====================================================================================
__global__ void __launch_bounds__(256, 2) wct_gemm(Pack pk)
{
    int mod = blockIdx.z;
    const float* W  = pk.p[g_role[5 + 2 * mod]];
    const float* Cb = pk.p[g_role[11 + mod]];

    __shared__ float As[16][132];
    __shared__ float Bs[16][132];

    int tid = threadIdx.x;
    int tx = tid & 15, ty = tid >> 4;
    int bm = blockIdx.y * 128;   // j
    int bn = blockIdx.x * 128;   // c

    float acc[8][8] = {};

    for (int kt = 0; kt < HID; kt += 16) {
        #pragma unroll
        for (int i = 0; i < 2; i++) {
            int f = tid + i * 256;
            int m = f >> 2, k4 = (f & 3) << 2;
            float4 v = *(const float4*)(W + (size_t)(bm + m) * HID + kt + k4);
            As[k4 + 0][m] = v.x; As[k4 + 1][m] = v.y;
            As[k4 + 2][m] = v.z; As[k4 + 3][m] = v.w;
        }
        #pragma unroll
        for (int i = 0; i < 2; i++) {
            int f = tid + i * 256;
            int c = f >> 2, k4 = (f & 3) << 2;
            float4 v = *(const float4*)(Cb + (size_t)(bn + c) * HID + kt + k4);
            Bs[k4 + 0][c] = v.x; Bs[k4 + 1][c] = v.y;
            Bs[k4 + 2][c] = v.z; Bs[k4 + 3][c] = v.w;
        }
        __syncthreads();

        #pragma unroll
        for (int k = 0; k < 16; k++) {
            float a[8], b[8];
            *(float4*)(a)     = *(const float4*)(&As[k][ty * 8]);
            *(float4*)(a + 4) = *(const float4*)(&As[k][ty * 8 + 4]);
            *(float4*)(b)     = *(const float4*)(&Bs[k][tx * 8]);
            *(float4*)(b + 4) = *(const float4*)(&Bs[k][tx * 8 + 4]);
            #pragma unroll
            for (int i = 0; i < 8; i++)
                #pragma unroll
                for (int j = 0; j < 8; j++)
                    acc[i][j] = fmaf(a[i], b[j], acc[i][j]);
        }
        __syncthreads();
    }

    #pragma unroll
    for (int i = 0; i < 8; i++) {
        int row = bm + ty * 8 + i;
        #pragma unroll
        for (int j4 = 0; j4 < 8; j4 += 4) {
            float4 o; float* op = (float*)&o;
            #pragma unroll
            for (int j = 0; j < 4; j++) op[j] = acc[i][j4 + j];
            *(float4*)(&g_D[mod][(size_t)row * CSIZE + bn + tx * 8 + j4]) = o;
        }
    }
}

// =====================================================================================
// Per-code prep for all 3 modalities in ONE launch (blockIdx.y = mod).
// =====================================================================================
__global__ void prep_kernel(Pack pk)
{
    int mod = blockIdx.y;
    const float* Cb   = pk.p[g_role[11 + mod]];
    const float* bvec = pk.p[g_role[6 + 2 * mod]];

    int row  = (blockIdx.x * blockDim.x + threadIdx.x) >> 5;
    int lane = threadIdx.x & 31;
    if (row >= CSIZE) return;
    const float* c = Cb + (size_t)row * HID;
    float s = 0.f, e = 0.f;
    for (int i = lane; i < HID; i += 32) {
        float cv = c[i];
        s = fmaf(cv, cv, s);
        e = fmaf(bvec[i], cv, e);
    }
    #pragma unroll
    for (int o = 16; o > 0; o >>= 1) {
        s += __shfl_xor_sync(0xFFFFFFFFu, s, o);
        e += __shfl_xor_sync(0xFFFFFFFFu, e, o);
    }
    if (lane == 0) {
        g_invn[mod][row] = 1.0f / sqrtf(s + 1e-12f);
        g_em[mod][row]   = e;
    }
}

// =====================================================================================
// VQ GEMM + argmax epilogue: S = g_H @ g_D[mod]; best (S+em[c])*invn[c] per row/chunk.
// =====================================================================================
__global__ void __launch_bounds__(256, 2) vq_gemm(int mod)
{
    __shared__ float As[16][132];
    __shared__ float Bs[16][132];
    __shared__ float rv[128][17];
    __shared__ int   ri[128][17];

    int tid = threadIdx.x;
    int tx = tid & 15, ty = tid >> 4;
    int bm = blockIdx.y * 128;
    int bn = blockIdx.x * 128;
    const float* D = g_D[mod];

    float acc[8][8] = {};

    for (int kt = 0; kt < HID; kt += 16) {
        #pragma unroll
        for (int i = 0; i < 2; i++) {
            int f = tid + i * 256;
            int m = f >> 2, k4 = (f & 3) << 2;
            float4 v = *(const float4*)(g_H + (size_t)(bm + m) * HID + kt + k4);
            As[k4 + 0][m] = v.x; As[k4 + 1][m] = v.y;
            As[k4 + 2][m] = v.z; As[k4 + 3][m] = v.w;
        }
        #pragma unroll
        for (int i = 0; i < 2; i++) {
            int f = tid + i * 256;
            int k = f >> 5, n4 = (f & 31) << 2;
            *(float4*)(&Bs[k][n4]) =
                *(const float4*)(D + (size_t)(kt + k) * CSIZE + bn + n4);
        }
        __syncthreads();

        #pragma unroll
        for (int k = 0; k < 16; k++) {
            float a[8], b[8];
            *(float4*)(a)     = *(const float4*)(&As[k][ty * 8]);
            *(float4*)(a + 4) = *(const float4*)(&As[k][ty * 8 + 4]);
            *(float4*)(b)     = *(const float4*)(&Bs[k][tx * 8]);
            *(float4*)(b + 4) = *(const float4*)(&Bs[k][tx * 8 + 4]);
            #pragma unroll
            for (int i = 0; i < 8; i++)
                #pragma unroll
                for (int j = 0; j < 8; j++)
                    acc[i][j] = fmaf(a[i], b[j], acc[i][j]);
        }
        __syncthreads();
    }

    #pragma unroll
    for (int i = 0; i < 8; i++) {
        float bv = -INFINITY; int bi = 0;
        #pragma unroll
        for (int j = 0; j < 8; j++) {
            int c = bn + tx * 8 + j;
            float v = (acc[i][j] + g_em[mod][c]) * g_invn[mod][c];
            if (v > bv) { bv = v; bi = c; }   // j ascending: strict > keeps lowest idx
        }
        rv[ty * 8 + i][tx] = bv;
        ri[ty * 8 + i][tx] = bi;
    }
    __syncthreads();

    if (tid < 128) {
        float best = rv[tid][0]; int bidx = ri[tid][0];
        #pragma unroll
        for (int t = 1; t < 16; t++) {
            float v = rv[tid][t];
            if (v > best) { best = v; bidx = ri[tid][t]; }
        }
        g_pval[mod][bm + tid][blockIdx.x] = best;
        g_pidx[mod][bm + tid][blockIdx.x] = bidx;
    }
}

// =====================================================================================
__global__ void reduce_codes(float* __restrict__ out)
{
    int n = blockIdx.x * blockDim.x + threadIdx.x;
    if (n >= NROWS) return;
    #pragma unroll
    for (int m = 0; m < 3; m++) {
        float bv = g_pval[m][n][0]; int bi = g_pidx[m][n][0];
        #pragma unroll
        for (int c = 1; c < NCHUNK; c++) {
            float v = g_pval[m][n][c];
            if (v > bv) { bv = v; bi = g_pidx[m][n][c]; }
        }
        out[n * 3 + m] = (float)bi;
    }
}

// =====================================================================================
__global__ void score_kernel(Pack pk)
{
    const float* ksw = pk.p[g_role[14]];
    const float* ksb = pk.p[g_role[15]];
    int warp = (blockIdx.x * blockDim.x + threadIdx.x) >> 5;
    int lane = threadIdx.x & 31;
    if (warp >= NROWS) return;
    const float* h = g_H + (size_t)warp * HID;
    double s = 0.0;
    for (int i = lane; i < HID; i += 32) s += (double)h[i] * (double)ksw[i];
    #pragma unroll
    for (int o = 16; o > 0; o >>= 1) s += __shfl_xor_sync(0xFFFFFFFFu, s, o);
    if (lane == 0) {
        float sc = (float)(s + (double)ksb[0]);
        unsigned int b = __float_as_uint(sc);
        b = (b & 0x80000000u) ? ~b : (b | 0x80000000u);   // totally-ordered float bits
        g_keys[warp] = ((unsigned long long)b << 32) | (0xFFFFFFFFu - (unsigned)warp);
    }
}

// =====================================================================================
__global__ void topk_kernel(float* __restrict__ out)
{
    __shared__ unsigned int hist[256];
    __shared__ unsigned long long sprefix;
    __shared__ int skk;
    __shared__ unsigned long long skeys[TOPM];
    __shared__ unsigned int scount;

    int tid = threadIdx.x;
    if (tid == 0) { sprefix = 0ULL; skk = TOPM; scount = 0u; }
    __syncthreads();

    for (int p = 7; p >= 0; p--) {
        if (tid < 256) hist[tid] = 0u;
        __syncthreads();
        unsigned long long pref = sprefix;
        for (int i = tid; i < NROWS; i += blockDim.x) {
            unsigned long long k = g_keys[i];
            bool match = (p == 7) || ((k >> ((p + 1) * 8)) == pref);
            if (match) atomicAdd(&hist[(unsigned)(k >> (p * 8)) & 0xFFu], 1u);
        }
        __syncthreads();
        if (tid == 0) {
            int kk = skk, c = 0, d;
            for (d = 255; d >= 0; d--) { c += (int)hist[d]; if (c >= kk) break; }
            skk = kk - (c - (int)hist[d]);
            sprefix = (sprefix << 8) | (unsigned long long)d;
        }
        __syncthreads();
    }
    unsigned long long thr = sprefix;   // exact 256th-largest key (keys unique)

    for (int i = tid; i < NROWS; i += blockDim.x) {
        unsigned long long k = g_keys[i];
        if (k >= thr) {
            unsigned p = atomicAdd(&scount, 1u);
            if (p < TOPM) skeys[p] = k;
        }
    }
    __syncthreads();

    for (int sz = 2; sz <= TOPM; sz <<= 1) {
        for (int st = sz >> 1; st > 0; st >>= 1) {
            __syncthreads();
            if (tid < TOPM) {
                int ixj = tid ^ st;
                if (ixj > tid) {
                    unsigned long long a = skeys[tid], b = skeys[ixj];
                    bool descBlk = ((tid & sz) == 0);
                    if (descBlk ? (a < b) : (a > b)) { skeys[tid] = b; skeys[ixj] = a; }
                }
            }
        }
    }
    __syncthreads();

    if (tid < TOPM) {
        unsigned idx = 0xFFFFFFFFu - (unsigned)(skeys[tid] & 0xFFFFFFFFu);
        out[NROWS * 3 + tid] = (float)idx;
        #pragma unroll
        for (int m = 0; m < 3; m++)
            out[NROWS * 3 + TOPM + tid * 3 + m] = out[(size_t)idx * 3 + m];
    }
}

// =====================================================================================
extern "C" void kernel_launch(void* const* d_in, const int* in_sizes, int n_in,
                              void* d_out, int out_size)
{
    Pack pk;
    Meta mt;
    int n16 = n_in < 16 ? n_in : 16;

    long long mn = 0x7FFFFFFFFFFFFFFFLL;
    for (int i = 0; i < n16; i++) {
        long long s = (long long)in_sizes[i];
        if (s < mn) mn = s;
    }
    long long div = (mn == 4) ? 4 : 1;

    for (int i = 0; i < 16; i++) {
        int src = i < n16 ? i : (n16 - 1);
        pk.p[i] = (const float*)d_in[src];
        mt.n[i] = (long long)in_sizes[src] / div;
    }

    mt.swap_tp = 0;
    if (mt.n[13] == 67108864LL) mt.swap_tp = 1;
    else if (mt.n[8] == 67108864LL && mt.n[0] == 1024LL) mt.swap_tp = 1;

    float* out = (float*)d_out;

    dim3 blk(256);
    dim3 gMLP(HID / 128,   NROWS / 128);      // (8, 256)
    dim3 gWCT(CSIZE / 128, HID / 128, 3);     // (16, 8, 3) - all 3 modalities
    dim3 gVQ (CSIZE / 128, NROWS / 128);      // (16, 256)
    dim3 gPREP(CSIZE / 8, 3);

    // launch order: first vq_gemm at position 6 => ncu -s 5 -c 1 profiles it
    classify_kernel<<<1, 256>>>(pk, mt);              // 1
    mlp_gemm<<<gMLP, blk>>>(pk, 0, INDIM);            // 2: relu(h0@W1+b1)
    mlp_gemm<<<gMLP, blk>>>(pk, 1, HID);              // 3: relu(h1@W2+b2)
    wct_gemm<<<gWCT, blk>>>(pk);                      // 4: D for all mods
    prep_kernel<<<gPREP, 256>>>(pk);                  // 5: invn/em all mods
    vq_gemm<<<gVQ, blk>>>(0);                         // 6: VQ mod 0  <-- profiled
    vq_gemm<<<gVQ, blk>>>(1);                         // 7
    vq_gemm<<<gVQ, blk>>>(2);                         // 8

    reduce_codes<<<NROWS / 256, 256>>>(out);
    score_kernel<<<NROWS / 8, 256>>>(pk);
    topk_kernel<<<1, 1024>>>(out);
}

// round 16
// speedup vs baseline: 3.8807x; 1.0405x over previous
#include <cuda_runtime.h>
#include <stdint.h>
#include <math.h>

#define NROWS 32768
#define INDIM 2048
#define HID   1024
#define CSIZE 2048
#define TOPM  256
#define NCHUNK (CSIZE/128)

// Role indices: 0:h0 1:W1 2:b1 3:W2 4:b2 5:Wm 6:bm 7:Wt 8:bt 9:Wp 10:bp
//               11:Cm 12:Ct 13:Cp 14:ksw 15:ksb
struct Pack { const float* p[16]; };
struct Meta { long long n[16]; int swap_tp; };

// ------------- scratch -------------
__device__ int   g_role[16];
__device__ float g_stat[16];
__device__ float g_h1[(size_t)NROWS * HID];
__device__ float g_H [(size_t)NROWS * HID];
__device__ float g_D [3][HID * CSIZE];
__device__ float g_invn[3][CSIZE];
__device__ float g_em  [3][CSIZE];
__device__ float g_pval[3][NROWS][NCHUNK];
__device__ int   g_pidx[3][NROWS][NCHUNK];
__device__ unsigned long long g_keys[NROWS];

// ---------------- helpers ----------------
__device__ __forceinline__ uint32_t smem_u32(const void* p) {
    uint32_t a;
    asm("{ .reg .u64 t; cvta.to.shared.u64 t, %1; cvt.u32.u64 %0, t; }" : "=r"(a) : "l"(p));
    return a;
}
__device__ __forceinline__ void cpasync16(uint32_t dst, const void* src) {
    asm volatile("cp.async.cg.shared.global [%0], [%1], 16;" :: "r"(dst), "l"(src) : "memory");
}
#define CP_COMMIT() asm volatile("cp.async.commit_group;" ::: "memory")

// pipeline tile geometry: BM=BN=128, BK=32
#define BK 32
#define A_ROW_B 144                 // 36 floats/row (32 data + 4 pad), 16B-aligned
#define B_ROW_B 528                 // 132 floats/row (128 data + 4 pad)
#define A_STG (128 * A_ROW_B)       // 18432 B
#define B_STG (BK * B_ROW_B)        // 16896 B
#define STG   (A_STG + B_STG)       // 35328 B
#define DSM_BYTES (2 * STG)         // 70656 B

// =====================================================================================
// classify (proven)
// =====================================================================================
__global__ void classify_kernel(Pack pk, Meta mt)
{
    __shared__ float red[256];
    int tid = threadIdx.x;
    for (int i = 0; i < 16; i++) {
        long long n = mt.n[i];
        long long cnt = n < 16384 ? n : 16384;
        float s = 0.f;
        const float* p = pk.p[i];
        for (long long j = tid; j < cnt; j += blockDim.x) s += fabsf(p[j]);
        red[tid] = s;
        __syncthreads();
        for (int o = 128; o > 0; o >>= 1) {
            if (tid < o) red[tid] += red[tid + o];
            __syncthreads();
        }
        if (tid == 0) g_stat[i] = red[0] / (float)cnt;
        __syncthreads();
    }
    if (tid == 0) {
        int big[4], nb = 0, mid[4], nm = 0, sml[6], ns = 0, ih0 = 0, iksb = 0;
        for (int i = 0; i < 16; i++) {
            long long n = mt.n[i];
            if      (n == 67108864LL) ih0 = i;
            else if (n == 2097152LL && nb < 4) big[nb++] = i;
            else if (n == 1048576LL && nm < 4) mid[nm++] = i;
            else if (n == 1024LL    && ns < 6) sml[ns++] = i;
            else if (n == 1LL)       iksb = i;
        }
        int w1 = big[0];
        for (int t = 1; t < 4; t++) if (g_stat[big[t]] < g_stat[w1]) w1 = big[t];
        int cA[3], ncv = 0;
        for (int t = 0; t < 4; t++) if (big[t] != w1) cA[ncv++] = big[t];
        int ksw = sml[0];
        for (int t = 1; t < 6; t++) if (g_stat[sml[t]] > g_stat[ksw]) ksw = sml[t];
        int bA[5], nbv = 0;
        for (int t = 0; t < 6; t++) if (sml[t] != ksw) bA[nbv++] = sml[t];

        int sw = mt.swap_tp;
        g_role[0]  = ih0;  g_role[1]  = w1;   g_role[2]  = bA[0];
        g_role[3]  = mid[0]; g_role[4]  = bA[1]; g_role[5]  = mid[1]; g_role[6]  = bA[2];
        g_role[7]  = sw ? mid[3] : mid[2];  g_role[8]  = sw ? bA[4]  : bA[3];
        g_role[9]  = sw ? mid[2] : mid[3];  g_role[10] = sw ? bA[3]  : bA[4];
        g_role[11] = cA[0];
        g_role[12] = sw ? cA[2] : cA[1];    g_role[13] = sw ? cA[1] : cA[2];
        g_role[14] = ksw;  g_role[15] = iksb;
    }
}

// =====================================================================================
// Pipelined mainloop core (shared by mlp_pipe and vq_pipe).
// A row-major [M,K]; B row-major k-major [K,N].  As kept row-major (cp.async direct);
// fragment loads use k-quads: a4[i] = As[row][q*4..+3] float4, broadcast across warp.
// =====================================================================================
__device__ __forceinline__ void gemm_mainloop(
    const unsigned char* dsm, uint32_t sb,
    const float* __restrict__ A, const float* __restrict__ B,
    int bm, int bn, int K, long ldb, float acc[8][8], int tid, int tx, int ty)
{
    int T = K / BK;

    auto load = [&](int t, int s) {
        uint32_t base = sb + s * STG;
        int kt = t * BK;
        #pragma unroll
        for (int i = 0; i < 4; i++) {
            int c = tid + i * 256;
            int r = c >> 3, c4 = c & 7;
            cpasync16(base + r * A_ROW_B + c4 * 16,
                      A + (size_t)(bm + r) * K + kt + c4 * 4);
        }
        #pragma unroll
        for (int i = 0; i < 4; i++) {
            int c = tid + i * 256;
            int r = c >> 5, c4 = c & 31;
            cpasync16(base + A_STG + r * B_ROW_B + c4 * 16,
                      B + (size_t)(kt + r) * ldb + bn + c4 * 4);
        }
        CP_COMMIT();
    };

    load(0, 0);

    for (int t = 0; t < T; t++) {
        if (t + 1 < T) {
            load(t + 1, (t + 1) & 1);
            asm volatile("cp.async.wait_group 1;" ::: "memory");
        } else {
            asm volatile("cp.async.wait_group 0;" ::: "memory");
        }
        __syncthreads();

        const unsigned char* sA = dsm + (t & 1) * STG;
        const unsigned char* sB = sA + A_STG;

        #pragma unroll
        for (int q = 0; q < BK / 4; q++) {
            float4 a4[8];
            #pragma unroll
            for (int i = 0; i < 8; i++)
                a4[i] = *(const float4*)(sA + (ty * 8 + i) * A_ROW_B + q * 16);
            #pragma unroll
            for (int kk = 0; kk < 4; kk++) {
                float4 b0 = *(const float4*)(sB + (q * 4 + kk) * B_ROW_B + tx * 32);
                float4 b1 = *(const float4*)(sB + (q * 4 + kk) * B_ROW_B + tx * 32 + 16);
                float b[8] = {b0.x, b0.y, b0.z, b0.w, b1.x, b1.y, b1.z, b1.w};
                #pragma unroll
                for (int i = 0; i < 8; i++) {
                    float av = (kk == 0) ? a4[i].x : (kk == 1) ? a4[i].y
                             : (kk == 2) ? a4[i].z : a4[i].w;
                    #pragma unroll
                    for (int j = 0; j < 8; j++)
                        acc[i][j] = fmaf(av, b[j], acc[i][j]);
                }
            }
        }
        __syncthreads();
    }
}

// =====================================================================================
// MLP GEMM (pipelined): dst = relu(A @ W + bias)
// =====================================================================================
__global__ void __launch_bounds__(256, 2) mlp_pipe(Pack pk, int which, int K)
{
    extern __shared__ __align__(16) unsigned char dsm[];
    uint32_t sb = smem_u32(dsm);

    const float* A    = which ? g_h1 : pk.p[g_role[0]];
    const float* W    = pk.p[g_role[which ? 3 : 1]];
    const float* bias = pk.p[g_role[which ? 4 : 2]];
    float*       Cd   = which ? g_H : g_h1;

    int tid = threadIdx.x, tx = tid & 15, ty = tid >> 4;
    int bm = blockIdx.y * 128, bn = blockIdx.x * 128;

    float acc[8][8] = {};
    gemm_mainloop(dsm, sb, A, W, bm, bn, K, HID, acc, tid, tx, ty);

    #pragma unroll
    for (int i = 0; i < 8; i++) {
        int row = bm + ty * 8 + i;
        #pragma unroll
        for (int j4 = 0; j4 < 8; j4 += 4) {
            float4 o; float* op = (float*)&o;
            #pragma unroll
            for (int j = 0; j < 4; j++) {
                float v = acc[i][j4 + j] + bias[bn + tx * 8 + j4 + j];
                op[j] = fmaxf(v, 0.f);
            }
            *(float4*)(Cd + (size_t)row * HID + bn + tx * 8 + j4) = o;
        }
    }
}

// =====================================================================================
// VQ GEMM (pipelined) + argmax epilogue
// =====================================================================================
__global__ void __launch_bounds__(256, 2) vq_pipe(int mod)
{
    extern __shared__ __align__(16) unsigned char dsm[];
    __shared__ float rv[128][17];
    __shared__ int   ri[128][17];
    uint32_t sb = smem_u32(dsm);

    int tid = threadIdx.x, tx = tid & 15, ty = tid >> 4;
    int bm = blockIdx.y * 128, bn = blockIdx.x * 128;

    float acc[8][8] = {};
    gemm_mainloop(dsm, sb, g_H, g_D[mod], bm, bn, HID, CSIZE, acc, tid, tx, ty);

    #pragma unroll
    for (int i = 0; i < 8; i++) {
        float bv = -INFINITY; int bi = 0;
        #pragma unroll
        for (int j = 0; j < 8; j++) {
            int c = bn + tx * 8 + j;
            float v = (acc[i][j] + g_em[mod][c]) * g_invn[mod][c];
            if (v > bv) { bv = v; bi = c; }   // j ascending: strict > keeps lowest idx
        }
        rv[ty * 8 + i][tx] = bv;
        ri[ty * 8 + i][tx] = bi;
    }
    __syncthreads();

    if (tid < 128) {
        float best = rv[tid][0]; int bidx = ri[tid][0];
        #pragma unroll
        for (int t = 1; t < 16; t++) {
            float v = rv[tid][t];
            if (v > best) { best = v; bidx = ri[tid][t]; }
        }
        g_pval[mod][bm + tid][blockIdx.x] = best;
        g_pidx[mod][bm + tid][blockIdx.x] = bidx;
    }
}

// =====================================================================================
// D = W @ C^T for all 3 modalities (proven round 15; small)
// =====================================================================================
__global__ void __launch_bounds__(256, 2) wct_gemm(Pack pk)
{
    int mod = blockIdx.z;
    const float* W  = pk.p[g_role[5 + 2 * mod]];
    const float* Cb = pk.p[g_role[11 + mod]];

    __shared__ float As[16][132];
    __shared__ float Bs[16][132];

    int tid = threadIdx.x;
    int tx = tid & 15, ty = tid >> 4;
    int bm = blockIdx.y * 128;
    int bn = blockIdx.x * 128;

    float acc[8][8] = {};

    for (int kt = 0; kt < HID; kt += 16) {
        #pragma unroll
        for (int i = 0; i < 2; i++) {
            int f = tid + i * 256;
            int m = f >> 2, k4 = (f & 3) << 2;
            float4 v = *(const float4*)(W + (size_t)(bm + m) * HID + kt + k4);
            As[k4 + 0][m] = v.x; As[k4 + 1][m] = v.y;
            As[k4 + 2][m] = v.z; As[k4 + 3][m] = v.w;
        }
        #pragma unroll
        for (int i = 0; i < 2; i++) {
            int f = tid + i * 256;
            int c = f >> 2, k4 = (f & 3) << 2;
            float4 v = *(const float4*)(Cb + (size_t)(bn + c) * HID + kt + k4);
            Bs[k4 + 0][c] = v.x; Bs[k4 + 1][c] = v.y;
            Bs[k4 + 2][c] = v.z; Bs[k4 + 3][c] = v.w;
        }
        __syncthreads();

        #pragma unroll
        for (int k = 0; k < 16; k++) {
            float a[8], b[8];
            *(float4*)(a)     = *(const float4*)(&As[k][ty * 8]);
            *(float4*)(a + 4) = *(const float4*)(&As[k][ty * 8 + 4]);
            *(float4*)(b)     = *(const float4*)(&Bs[k][tx * 8]);
            *(float4*)(b + 4) = *(const float4*)(&Bs[k][tx * 8 + 4]);
            #pragma unroll
            for (int i = 0; i < 8; i++)
                #pragma unroll
                for (int j = 0; j < 8; j++)
                    acc[i][j] = fmaf(a[i], b[j], acc[i][j]);
        }
        __syncthreads();
    }

    #pragma unroll
    for (int i = 0; i < 8; i++) {
        int row = bm + ty * 8 + i;
        #pragma unroll
        for (int j4 = 0; j4 < 8; j4 += 4) {
            float4 o; float* op = (float*)&o;
            #pragma unroll
            for (int j = 0; j < 4; j++) op[j] = acc[i][j4 + j];
            *(float4*)(&g_D[mod][(size_t)row * CSIZE + bn + tx * 8 + j4]) = o;
        }
    }
}

// =====================================================================================
__global__ void prep_kernel(Pack pk)
{
    int mod = blockIdx.y;
    const float* Cb   = pk.p[g_role[11 + mod]];
    const float* bvec = pk.p[g_role[6 + 2 * mod]];

    int row  = (blockIdx.x * blockDim.x + threadIdx.x) >> 5;
    int lane = threadIdx.x & 31;
    if (row >= CSIZE) return;
    const float* c = Cb + (size_t)row * HID;
    float s = 0.f, e = 0.f;
    for (int i = lane; i < HID; i += 32) {
        float cv = c[i];
        s = fmaf(cv, cv, s);
        e = fmaf(bvec[i], cv, e);
    }
    #pragma unroll
    for (int o = 16; o > 0; o >>= 1) {
        s += __shfl_xor_sync(0xFFFFFFFFu, s, o);
        e += __shfl_xor_sync(0xFFFFFFFFu, e, o);
    }
    if (lane == 0) {
        g_invn[mod][row] = 1.0f / sqrtf(s + 1e-12f);
        g_em[mod][row]   = e;
    }
}

// =====================================================================================
__global__ void reduce_codes(float* __restrict__ out)
{
    int n = blockIdx.x * blockDim.x + threadIdx.x;
    if (n >= NROWS) return;
    #pragma unroll
    for (int m = 0; m < 3; m++) {
        float bv = g_pval[m][n][0]; int bi = g_pidx[m][n][0];
        #pragma unroll
        for (int c = 1; c < NCHUNK; c++) {
            float v = g_pval[m][n][c];
            if (v > bv) { bv = v; bi = g_pidx[m][n][c]; }
        }
        out[n * 3 + m] = (float)bi;
    }
}

// =====================================================================================
__global__ void score_kernel(Pack pk)
{
    const float* ksw = pk.p[g_role[14]];
    const float* ksb = pk.p[g_role[15]];
    int warp = (blockIdx.x * blockDim.x + threadIdx.x) >> 5;
    int lane = threadIdx.x & 31;
    if (warp >= NROWS) return;
    const float* h = g_H + (size_t)warp * HID;
    double s = 0.0;
    for (int i = lane; i < HID; i += 32) s += (double)h[i] * (double)ksw[i];
    #pragma unroll
    for (int o = 16; o > 0; o >>= 1) s += __shfl_xor_sync(0xFFFFFFFFu, s, o);
    if (lane == 0) {
        float sc = (float)(s + (double)ksb[0]);
        unsigned int b = __float_as_uint(sc);
        b = (b & 0x80000000u) ? ~b : (b | 0x80000000u);
        g_keys[warp] = ((unsigned long long)b << 32) | (0xFFFFFFFFu - (unsigned)warp);
    }
}

// =====================================================================================
__global__ void topk_kernel(float* __restrict__ out)
{
    __shared__ unsigned int hist[256];
    __shared__ unsigned long long sprefix;
    __shared__ int skk;
    __shared__ unsigned long long skeys[TOPM];
    __shared__ unsigned int scount;

    int tid = threadIdx.x;
    if (tid == 0) { sprefix = 0ULL; skk = TOPM; scount = 0u; }
    __syncthreads();

    for (int p = 7; p >= 0; p--) {
        if (tid < 256) hist[tid] = 0u;
        __syncthreads();
        unsigned long long pref = sprefix;
        for (int i = tid; i < NROWS; i += blockDim.x) {
            unsigned long long k = g_keys[i];
            bool match = (p == 7) || ((k >> ((p + 1) * 8)) == pref);
            if (match) atomicAdd(&hist[(unsigned)(k >> (p * 8)) & 0xFFu], 1u);
        }
        __syncthreads();
        if (tid == 0) {
            int kk = skk, c = 0, d;
            for (d = 255; d >= 0; d--) { c += (int)hist[d]; if (c >= kk) break; }
            skk = kk - (c - (int)hist[d]);
            sprefix = (sprefix << 8) | (unsigned long long)d;
        }
        __syncthreads();
    }
    unsigned long long thr = sprefix;

    for (int i = tid; i < NROWS; i += blockDim.x) {
        unsigned long long k = g_keys[i];
        if (k >= thr) {
            unsigned p = atomicAdd(&scount, 1u);
            if (p < TOPM) skeys[p] = k;
        }
    }
    __syncthreads();

    for (int sz = 2; sz <= TOPM; sz <<= 1) {
        for (int st = sz >> 1; st > 0; st >>= 1) {
            __syncthreads();
            if (tid < TOPM) {
                int ixj = tid ^ st;
                if (ixj > tid) {
                    unsigned long long a = skeys[tid], b = skeys[ixj];
                    bool descBlk = ((tid & sz) == 0);
                    if (descBlk ? (a < b) : (a > b)) { skeys[tid] = b; skeys[ixj] = a; }
                }
            }
        }
    }
    __syncthreads();

    if (tid < TOPM) {
        unsigned idx = 0xFFFFFFFFu - (unsigned)(skeys[tid] & 0xFFFFFFFFu);
        out[NROWS * 3 + tid] = (float)idx;
        #pragma unroll
        for (int m = 0; m < 3; m++)
            out[NROWS * 3 + TOPM + tid * 3 + m] = out[(size_t)idx * 3 + m];
    }
}

// =====================================================================================
extern "C" void kernel_launch(void* const* d_in, const int* in_sizes, int n_in,
                              void* d_out, int out_size)
{
    Pack pk;
    Meta mt;
    int n16 = n_in < 16 ? n_in : 16;

    long long mn = 0x7FFFFFFFFFFFFFFFLL;
    for (int i = 0; i < n16; i++) {
        long long s = (long long)in_sizes[i];
        if (s < mn) mn = s;
    }
    long long div = (mn == 4) ? 4 : 1;

    for (int i = 0; i < 16; i++) {
        int src = i < n16 ? i : (n16 - 1);
        pk.p[i] = (const float*)d_in[src];
        mt.n[i] = (long long)in_sizes[src] / div;
    }

    mt.swap_tp = 0;
    if (mt.n[13] == 67108864LL) mt.swap_tp = 1;
    else if (mt.n[8] == 67108864LL && mt.n[0] == 1024LL) mt.swap_tp = 1;

    float* out = (float*)d_out;

    static int smem_set = 0;
    if (!smem_set) {
        cudaFuncSetAttribute(mlp_pipe, cudaFuncAttributeMaxDynamicSharedMemorySize, DSM_BYTES);
        cudaFuncSetAttribute(vq_pipe,  cudaFuncAttributeMaxDynamicSharedMemorySize, DSM_BYTES);
        smem_set = 1;
    }

    dim3 blk(256);
    dim3 gMLP(HID / 128,   NROWS / 128);      // (8, 256)
    dim3 gWCT(CSIZE / 128, HID / 128, 3);     // (16, 8, 3)
    dim3 gVQ (CSIZE / 128, NROWS / 128);      // (16, 256)
    dim3 gPREP(CSIZE / 8, 3);

    classify_kernel<<<1, 256>>>(pk, mt);                  // 1
    mlp_pipe<<<gMLP, blk, DSM_BYTES>>>(pk, 0, INDIM);     // 2
    mlp_pipe<<<gMLP, blk, DSM_BYTES>>>(pk, 1, HID);       // 3
    wct_gemm<<<gWCT, blk>>>(pk);                          // 4
    prep_kernel<<<gPREP, 256>>>(pk);                      // 5
    vq_pipe<<<gVQ, blk, DSM_BYTES>>>(0);                  // 6  <-- profiled
    vq_pipe<<<gVQ, blk, DSM_BYTES>>>(1);                  // 7
    vq_pipe<<<gVQ, blk, DSM_BYTES>>>(2);                  // 8

    reduce_codes<<<NROWS / 256, 256>>>(out);
    score_kernel<<<NROWS / 8, 256>>>(pk);
    topk_kernel<<<1, 1024>>>(out);
}

// round 17
// speedup vs baseline: 4.1184x; 1.0612x over previous
#include <cuda_runtime.h>
#include <stdint.h>
#include <math.h>

#define NROWS 32768
#define INDIM 2048
#define HID   1024
#define CSIZE 2048
#define TOPM  256
#define NCHUNK (CSIZE/128)

// Role indices: 0:h0 1:W1 2:b1 3:W2 4:b2 5:Wm 6:bm 7:Wt 8:bt 9:Wp 10:bp
//               11:Cm 12:Ct 13:Cp 14:ksw 15:ksb
struct Pack { const float* p[16]; };
struct Meta { long long n[16]; int swap_tp; };

// ------------- scratch -------------
__device__ int   g_role[16];
__device__ float g_stat[16];
__device__ float g_h0T[(size_t)INDIM * NROWS];   // h0 transposed  [k][n] 256 MB
__device__ float g_h1T[(size_t)HID * NROWS];     // h1 transposed  128 MB
__device__ float g_HT [(size_t)HID * NROWS];     // H transposed   128 MB
__device__ float g_H  [(size_t)NROWS * HID];     // H row-major (score)  128 MB
__device__ float g_D  [3][HID * CSIZE];          // k-major B for VQ
__device__ float g_invn[3][CSIZE];
__device__ float g_em  [3][CSIZE];
__device__ float g_pval[3][NROWS][NCHUNK];
__device__ int   g_pidx[3][NROWS][NCHUNK];
__device__ unsigned long long g_keys[NROWS];

// ---------------- helpers ----------------
__device__ __forceinline__ uint32_t smem_u32(const void* p) {
    uint32_t a;
    asm("{ .reg .u64 t; cvta.to.shared.u64 t, %1; cvt.u32.u64 %0, t; }" : "=r"(a) : "l"(p));
    return a;
}
__device__ __forceinline__ void cpasync16(uint32_t dst, const void* src) {
    asm volatile("cp.async.cg.shared.global [%0], [%1], 16;" :: "r"(dst), "l"(src) : "memory");
}
#define CP_COMMIT() asm volatile("cp.async.commit_group;" ::: "memory")

// tile geometry: BM=BN=128, BK=32; both smem tiles k-major 32 x (128+4)
#define BK 32
#define ROW_B 528                    // 132 floats * 4B
#define T_STG (BK * ROW_B)           // 16896 B per operand tile
#define STG   (2 * T_STG)            // 33792 B per stage
#define DSM_BYTES (2 * STG)          // 67584 B  (== 128x132 fp32 bounce tile)

// =====================================================================================
// classify (proven)
// =====================================================================================
__global__ void classify_kernel(Pack pk, Meta mt)
{
    __shared__ float red[256];
    int tid = threadIdx.x;
    for (int i = 0; i < 16; i++) {
        long long n = mt.n[i];
        long long cnt = n < 16384 ? n : 16384;
        float s = 0.f;
        const float* p = pk.p[i];
        for (long long j = tid; j < cnt; j += blockDim.x) s += fabsf(p[j]);
        red[tid] = s;
        __syncthreads();
        for (int o = 128; o > 0; o >>= 1) {
            if (tid < o) red[tid] += red[tid + o];
            __syncthreads();
        }
        if (tid == 0) g_stat[i] = red[0] / (float)cnt;
        __syncthreads();
    }
    if (tid == 0) {
        int big[4], nb = 0, mid[4], nm = 0, sml[6], ns = 0, ih0 = 0, iksb = 0;
        for (int i = 0; i < 16; i++) {
            long long n = mt.n[i];
            if      (n == 67108864LL) ih0 = i;
            else if (n == 2097152LL && nb < 4) big[nb++] = i;
            else if (n == 1048576LL && nm < 4) mid[nm++] = i;
            else if (n == 1024LL    && ns < 6) sml[ns++] = i;
            else if (n == 1LL)       iksb = i;
        }
        int w1 = big[0];
        for (int t = 1; t < 4; t++) if (g_stat[big[t]] < g_stat[w1]) w1 = big[t];
        int cA[3], ncv = 0;
        for (int t = 0; t < 4; t++) if (big[t] != w1) cA[ncv++] = big[t];
        int ksw = sml[0];
        for (int t = 1; t < 6; t++) if (g_stat[sml[t]] > g_stat[ksw]) ksw = sml[t];
        int bA[5], nbv = 0;
        for (int t = 0; t < 6; t++) if (sml[t] != ksw) bA[nbv++] = sml[t];

        int sw = mt.swap_tp;
        g_role[0]  = ih0;  g_role[1]  = w1;   g_role[2]  = bA[0];
        g_role[3]  = mid[0]; g_role[4]  = bA[1]; g_role[5]  = mid[1]; g_role[6]  = bA[2];
        g_role[7]  = sw ? mid[3] : mid[2];  g_role[8]  = sw ? bA[4]  : bA[3];
        g_role[9]  = sw ? mid[2] : mid[3];  g_role[10] = sw ? bA[3]  : bA[4];
        g_role[11] = cA[0];
        g_role[12] = sw ? cA[2] : cA[1];    g_role[13] = sw ? cA[1] : cA[2];
        g_role[14] = ksw;  g_role[15] = iksb;
    }
}

// =====================================================================================
// h0 transpose: [NROWS, INDIM] -> g_h0T [INDIM, NROWS].  32x32 smem tiles.
// =====================================================================================
__global__ void transpose_h0(Pack pk)
{
    __shared__ float s[32][33];
    const float* src = pk.p[g_role[0]];
    int tx = threadIdx.x & 31, ty8 = threadIdx.x >> 5;    // block 256 = 32x8
    int bx = blockIdx.x * 32, by = blockIdx.y * 32;       // bx: col(INDIM), by: row(NROWS)
    #pragma unroll
    for (int i = 0; i < 4; i++) {
        int r = ty8 + i * 8;
        s[r][tx] = src[(size_t)(by + r) * INDIM + bx + tx];
    }
    __syncthreads();
    #pragma unroll
    for (int i = 0; i < 4; i++) {
        int r = ty8 + i * 8;
        g_h0T[(size_t)(bx + r) * NROWS + by + tx] = s[tx][r];
    }
}

// =====================================================================================
// Pipelined k-major mainloop. AT [K, M] (ldaT), B [K, N] (ldb): both cp.async direct
// into k-major smem.  Fragment loads: 4 LDS.128 per k, no staging registers.
// FFMA order: k ascending over full K -> bit-identical to proven r10/r16 results.
// =====================================================================================
__device__ __forceinline__ void mainloop_T(
    const unsigned char* dsm, uint32_t sb,
    const float* __restrict__ AT, const float* __restrict__ B,
    int bm, int bn, int K, long ldaT, long ldb,
    float acc[8][8], int tid, int tx, int ty)
{
    int T = K / BK;

    auto load = [&](int t, int s) {
        uint32_t base = sb + s * STG;
        int kt = t * BK;
        #pragma unroll
        for (int i = 0; i < 4; i++) {
            int idx = tid + i * 256;              // 0..1023
            int r = idx >> 5, c4 = idx & 31;      // 32 rows x 32 float4
            cpasync16(base + r * ROW_B + c4 * 16,
                      AT + (size_t)(kt + r) * ldaT + bm + c4 * 4);
        }
        #pragma unroll
        for (int i = 0; i < 4; i++) {
            int idx = tid + i * 256;
            int r = idx >> 5, c4 = idx & 31;
            cpasync16(base + T_STG + r * ROW_B + c4 * 16,
                      B + (size_t)(kt + r) * ldb + bn + c4 * 4);
        }
        CP_COMMIT();
    };

    load(0, 0);

    for (int t = 0; t < T; t++) {
        if (t + 1 < T) {
            load(t + 1, (t + 1) & 1);
            asm volatile("cp.async.wait_group 1;" ::: "memory");
        } else {
            asm volatile("cp.async.wait_group 0;" ::: "memory");
        }
        __syncthreads();

        const unsigned char* sA = dsm + (t & 1) * STG;
        const unsigned char* sB = sA + T_STG;

        #pragma unroll
        for (int k = 0; k < BK; k++) {
            float a[8], b[8];
            *(float4*)(a)     = *(const float4*)(sA + k * ROW_B + ty * 32);
            *(float4*)(a + 4) = *(const float4*)(sA + k * ROW_B + ty * 32 + 16);
            *(float4*)(b)     = *(const float4*)(sB + k * ROW_B + tx * 32);
            *(float4*)(b + 4) = *(const float4*)(sB + k * ROW_B + tx * 32 + 16);
            #pragma unroll
            for (int i = 0; i < 8; i++)
                #pragma unroll
                for (int j = 0; j < 8; j++)
                    acc[i][j] = fmaf(a[i], b[j], acc[i][j]);
        }
        __syncthreads();
    }
}

// transposed tile writer: acc(m-i, n-j) -> dstT[n][m] via smem bounce (coalesced out)
__device__ __forceinline__ void write_T(
    unsigned char* dsm, float* __restrict__ dstT, long ldT,
    int bm, int bn, const float vals[8][8], int tid, int tx, int ty)
{
    float* bounce = (float*)dsm;
    __syncthreads();                        // mainloop smem fully consumed
    #pragma unroll
    for (int i = 0; i < 8; i++)
        #pragma unroll
        for (int j = 0; j < 8; j++)
            bounce[(size_t)(tx * 8 + j) * 132 + ty * 8 + i] = vals[i][j];
    __syncthreads();
    #pragma unroll
    for (int p = 0; p < 4; p++) {
        int r = p * 32 + (tid >> 3);        // 0..127  (n-local)
        int c = (tid & 7) * 16;             // 8 threads x 16 floats = 128
        float4* dst = (float4*)(dstT + (size_t)(bn + r) * ldT + bm + c);
        const float* srcb = bounce + (size_t)r * 132 + c;
        #pragma unroll
        for (int q = 0; q < 4; q++)
            dst[q] = *(const float4*)(srcb + q * 4);
    }
}

// =====================================================================================
// MLP GEMM (pipelined, k-major A): out = relu(A @ W + b)
// which 0: A=g_h0T -> writes g_h1T (transposed only)
// which 1: A=g_h1T -> writes g_HT (transposed) + g_H (row-major, for score)
// =====================================================================================
__global__ void __launch_bounds__(256, 2) mlp_pipe(Pack pk, int which, int K)
{
    extern __shared__ __align__(16) unsigned char dsm[];
    uint32_t sb = smem_u32(dsm);

    const float* AT   = which ? g_h1T : g_h0T;
    const float* W    = pk.p[g_role[which ? 3 : 1]];
    const float* bias = pk.p[g_role[which ? 4 : 2]];

    int tid = threadIdx.x, tx = tid & 15, ty = tid >> 4;
    int bm = blockIdx.y * 128, bn = blockIdx.x * 128;

    float acc[8][8] = {};
    mainloop_T(dsm, sb, AT, W, bm, bn, K, NROWS, HID, acc, tid, tx, ty);

    // bias + relu in-place
    #pragma unroll
    for (int i = 0; i < 8; i++)
        #pragma unroll
        for (int j = 0; j < 8; j++)
            acc[i][j] = fmaxf(acc[i][j] + bias[bn + tx * 8 + j], 0.f);

    if (which == 1) {
        // row-major copy for score_kernel
        #pragma unroll
        for (int i = 0; i < 8; i++) {
            int row = bm + ty * 8 + i;
            #pragma unroll
            for (int j4 = 0; j4 < 8; j4 += 4) {
                float4 o; float* op = (float*)&o;
                #pragma unroll
                for (int j = 0; j < 4; j++) op[j] = acc[i][j4 + j];
                *(float4*)(g_H + (size_t)row * HID + bn + tx * 8 + j4) = o;
            }
        }
    }
    write_T(dsm, which ? g_HT : g_h1T, NROWS, bm, bn, acc, tid, tx, ty);
}

// =====================================================================================
// VQ GEMM (pipelined, k-major A=g_HT) + argmax epilogue; 3 modalities in one launch
// =====================================================================================
__global__ void __launch_bounds__(256, 2) vq_pipe()
{
    extern __shared__ __align__(16) unsigned char dsm[];
    __shared__ float rv[128][17];
    __shared__ int   ri[128][17];
    uint32_t sb = smem_u32(dsm);

    int mod = blockIdx.x >> 4;
    int chunk = blockIdx.x & 15;
    int tid = threadIdx.x, tx = tid & 15, ty = tid >> 4;
    int bm = blockIdx.y * 128, bn = chunk * 128;

    float acc[8][8] = {};
    mainloop_T(dsm, sb, g_HT, g_D[mod], bm, bn, HID, NROWS, CSIZE, acc, tid, tx, ty);

    #pragma unroll
    for (int i = 0; i < 8; i++) {
        float bv = -INFINITY; int bi = 0;
        #pragma unroll
        for (int j = 0; j < 8; j++) {
            int c = bn + tx * 8 + j;
            float v = (acc[i][j] + g_em[mod][c]) * g_invn[mod][c];
            if (v > bv) { bv = v; bi = c; }   // j ascending: keeps lowest idx
        }
        rv[ty * 8 + i][tx] = bv;
        ri[ty * 8 + i][tx] = bi;
    }
    __syncthreads();

    if (tid < 128) {
        float best = rv[tid][0]; int bidx = ri[tid][0];
        #pragma unroll
        for (int t = 1; t < 16; t++) {
            float v = rv[tid][t];
            if (v > best) { best = v; bidx = ri[tid][t]; }
        }
        g_pval[mod][bm + tid][chunk] = best;
        g_pidx[mod][bm + tid][chunk] = bidx;
    }
}

// =====================================================================================
// D = W @ C^T, all 3 modalities (proven)
// =====================================================================================
__global__ void __launch_bounds__(256, 2) wct_gemm(Pack pk)
{
    int mod = blockIdx.z;
    const float* W  = pk.p[g_role[5 + 2 * mod]];
    const float* Cb = pk.p[g_role[11 + mod]];

    __shared__ float As[16][132];
    __shared__ float Bs[16][132];

    int tid = threadIdx.x;
    int tx = tid & 15, ty = tid >> 4;
    int bm = blockIdx.y * 128;
    int bn = blockIdx.x * 128;

    float acc[8][8] = {};

    for (int kt = 0; kt < HID; kt += 16) {
        #pragma unroll
        for (int i = 0; i < 2; i++) {
            int f = tid + i * 256;
            int m = f >> 2, k4 = (f & 3) << 2;
            float4 v = *(const float4*)(W + (size_t)(bm + m) * HID + kt + k4);
            As[k4 + 0][m] = v.x; As[k4 + 1][m] = v.y;
            As[k4 + 2][m] = v.z; As[k4 + 3][m] = v.w;
        }
        #pragma unroll
        for (int i = 0; i < 2; i++) {
            int f = tid + i * 256;
            int c = f >> 2, k4 = (f & 3) << 2;
            float4 v = *(const float4*)(Cb + (size_t)(bn + c) * HID + kt + k4);
            Bs[k4 + 0][c] = v.x; Bs[k4 + 1][c] = v.y;
            Bs[k4 + 2][c] = v.z; Bs[k4 + 3][c] = v.w;
        }
        __syncthreads();

        #pragma unroll
        for (int k = 0; k < 16; k++) {
            float a[8], b[8];
            *(float4*)(a)     = *(const float4*)(&As[k][ty * 8]);
            *(float4*)(a + 4) = *(const float4*)(&As[k][ty * 8 + 4]);
            *(float4*)(b)     = *(const float4*)(&Bs[k][tx * 8]);
            *(float4*)(b + 4) = *(const float4*)(&Bs[k][tx * 8 + 4]);
            #pragma unroll
            for (int i = 0; i < 8; i++)
                #pragma unroll
                for (int j = 0; j < 8; j++)
                    acc[i][j] = fmaf(a[i], b[j], acc[i][j]);
        }
        __syncthreads();
    }

    #pragma unroll
    for (int i = 0; i < 8; i++) {
        int row = bm + ty * 8 + i;
        #pragma unroll
        for (int j4 = 0; j4 < 8; j4 += 4) {
            float4 o; float* op = (float*)&o;
            #pragma unroll
            for (int j = 0; j < 4; j++) op[j] = acc[i][j4 + j];
            *(float4*)(&g_D[mod][(size_t)row * CSIZE + bn + tx * 8 + j4]) = o;
        }
    }
}

// =====================================================================================
__global__ void prep_kernel(Pack pk)
{
    int mod = blockIdx.y;
    const float* Cb   = pk.p[g_role[11 + mod]];
    const float* bvec = pk.p[g_role[6 + 2 * mod]];

    int row  = (blockIdx.x * blockDim.x + threadIdx.x) >> 5;
    int lane = threadIdx.x & 31;
    if (row >= CSIZE) return;
    const float* c = Cb + (size_t)row * HID;
    float s = 0.f, e = 0.f;
    for (int i = lane; i < HID; i += 32) {
        float cv = c[i];
        s = fmaf(cv, cv, s);
        e = fmaf(bvec[i], cv, e);
    }
    #pragma unroll
    for (int o = 16; o > 0; o >>= 1) {
        s += __shfl_xor_sync(0xFFFFFFFFu, s, o);
        e += __shfl_xor_sync(0xFFFFFFFFu, e, o);
    }
    if (lane == 0) {
        g_invn[mod][row] = 1.0f / sqrtf(s + 1e-12f);
        g_em[mod][row]   = e;
    }
}

// =====================================================================================
__global__ void reduce_codes(float* __restrict__ out)
{
    int n = blockIdx.x * blockDim.x + threadIdx.x;
    if (n >= NROWS) return;
    #pragma unroll
    for (int m = 0; m < 3; m++) {
        float bv = g_pval[m][n][0]; int bi = g_pidx[m][n][0];
        #pragma unroll
        for (int c = 1; c < NCHUNK; c++) {
            float v = g_pval[m][n][c];
            if (v > bv) { bv = v; bi = g_pidx[m][n][c]; }
        }
        out[n * 3 + m] = (float)bi;
    }
}

// =====================================================================================
__global__ void score_kernel(Pack pk)
{
    const float* ksw = pk.p[g_role[14]];
    const float* ksb = pk.p[g_role[15]];
    int warp = (blockIdx.x * blockDim.x + threadIdx.x) >> 5;
    int lane = threadIdx.x & 31;
    if (warp >= NROWS) return;
    const float* h = g_H + (size_t)warp * HID;
    double s = 0.0;
    for (int i = lane; i < HID; i += 32) s += (double)h[i] * (double)ksw[i];
    #pragma unroll
    for (int o = 16; o > 0; o >>= 1) s += __shfl_xor_sync(0xFFFFFFFFu, s, o);
    if (lane == 0) {
        float sc = (float)(s + (double)ksb[0]);
        unsigned int b = __float_as_uint(sc);
        b = (b & 0x80000000u) ? ~b : (b | 0x80000000u);
        g_keys[warp] = ((unsigned long long)b << 32) | (0xFFFFFFFFu - (unsigned)warp);
    }
}

// =====================================================================================
__global__ void topk_kernel(float* __restrict__ out)
{
    __shared__ unsigned int hist[256];
    __shared__ unsigned long long sprefix;
    __shared__ int skk;
    __shared__ unsigned long long skeys[TOPM];
    __shared__ unsigned int scount;

    int tid = threadIdx.x;
    if (tid == 0) { sprefix = 0ULL; skk = TOPM; scount = 0u; }
    __syncthreads();

    for (int p = 7; p >= 0; p--) {
        if (tid < 256) hist[tid] = 0u;
        __syncthreads();
        unsigned long long pref = sprefix;
        for (int i = tid; i < NROWS; i += blockDim.x) {
            unsigned long long k = g_keys[i];
            bool match = (p == 7) || ((k >> ((p + 1) * 8)) == pref);
            if (match) atomicAdd(&hist[(unsigned)(k >> (p * 8)) & 0xFFu], 1u);
        }
        __syncthreads();
        if (tid == 0) {
            int kk = skk, c = 0, d;
            for (d = 255; d >= 0; d--) { c += (int)hist[d]; if (c >= kk) break; }
            skk = kk - (c - (int)hist[d]);
            sprefix = (sprefix << 8) | (unsigned long long)d;
        }
        __syncthreads();
    }
    unsigned long long thr = sprefix;

    for (int i = tid; i < NROWS; i += blockDim.x) {
        unsigned long long k = g_keys[i];
        if (k >= thr) {
            unsigned p = atomicAdd(&scount, 1u);
            if (p < TOPM) skeys[p] = k;
        }
    }
    __syncthreads();

    for (int sz = 2; sz <= TOPM; sz <<= 1) {
        for (int st = sz >> 1; st > 0; st >>= 1) {
            __syncthreads();
            if (tid < TOPM) {
                int ixj = tid ^ st;
                if (ixj > tid) {
                    unsigned long long a = skeys[tid], b = skeys[ixj];
                    bool descBlk = ((tid & sz) == 0);
                    if (descBlk ? (a < b) : (a > b)) { skeys[tid] = b; skeys[ixj] = a; }
                }
            }
        }
    }
    __syncthreads();

    if (tid < TOPM) {
        unsigned idx = 0xFFFFFFFFu - (unsigned)(skeys[tid] & 0xFFFFFFFFu);
        out[NROWS * 3 + tid] = (float)idx;
        #pragma unroll
        for (int m = 0; m < 3; m++)
            out[NROWS * 3 + TOPM + tid * 3 + m] = out[(size_t)idx * 3 + m];
    }
}

// =====================================================================================
extern "C" void kernel_launch(void* const* d_in, const int* in_sizes, int n_in,
                              void* d_out, int out_size)
{
    Pack pk;
    Meta mt;
    int n16 = n_in < 16 ? n_in : 16;

    long long mn = 0x7FFFFFFFFFFFFFFFLL;
    for (int i = 0; i < n16; i++) {
        long long s = (long long)in_sizes[i];
        if (s < mn) mn = s;
    }
    long long div = (mn == 4) ? 4 : 1;

    for (int i = 0; i < 16; i++) {
        int src = i < n16 ? i : (n16 - 1);
        pk.p[i] = (const float*)d_in[src];
        mt.n[i] = (long long)in_sizes[src] / div;
    }

    mt.swap_tp = 0;
    if (mt.n[13] == 67108864LL) mt.swap_tp = 1;
    else if (mt.n[8] == 67108864LL && mt.n[0] == 1024LL) mt.swap_tp = 1;

    float* out = (float*)d_out;

    cudaFuncSetAttribute(mlp_pipe, cudaFuncAttributeMaxDynamicSharedMemorySize, DSM_BYTES);
    cudaFuncSetAttribute(vq_pipe,  cudaFuncAttributeMaxDynamicSharedMemorySize, DSM_BYTES);

    dim3 blk(256);
    dim3 gTR (INDIM / 32, NROWS / 32);        // (64, 1024)
    dim3 gMLP(HID / 128,   NROWS / 128);      // (8, 256)
    dim3 gWCT(CSIZE / 128, HID / 128, 3);     // (16, 8, 3)
    dim3 gVQ (3 * NCHUNK,  NROWS / 128);      // (48, 256): all modalities fused
    dim3 gPREP(CSIZE / 8, 3);

    classify_kernel<<<1, 256>>>(pk, mt);                  // 1
    transpose_h0<<<gTR, 256>>>(pk);                       // 2
    mlp_pipe<<<gMLP, blk, DSM_BYTES>>>(pk, 0, INDIM);     // 3
    mlp_pipe<<<gMLP, blk, DSM_BYTES>>>(pk, 1, HID);       // 4
    wct_gemm<<<gWCT, blk>>>(pk);                          // 5
    prep_kernel<<<gPREP, 256>>>(pk);                      // 6
    vq_pipe<<<gVQ, blk, DSM_BYTES>>>();                   // 7

    reduce_codes<<<NROWS / 256, 256>>>(out);
    score_kernel<<<NROWS / 8, 256>>>(pk);
    topk_kernel<<<1, 1024>>>(out);
}